// round 3
// baseline (speedup 1.0000x reference)
#include <cuda_runtime.h>
#include <math.h>

#define NN    8192
#define DD    128
#define VV    2
#define TILE  128
#define NT    (NN / TILE)      // 64 tiles per dim
#define KC    16               // K-chunk
#define ASTR  132              // smem stride for A/B k-major tiles (padded)
#define SSTR  129              // smem stride for staged S tile (129 % 32 == 1 -> conflict-free both orders)

// Scratch: normalized views, [v][n][d] layout (8 MB), plus the double accumulator.
__device__ float  g_xn[VV][NN][DD];
__device__ double g_acc;

// ---------------------------------------------------------------------------
// Zero the accumulator (must run every launch for determinism)
// ---------------------------------------------------------------------------
__global__ void zero_acc_kernel() { g_acc = 0.0; }

// ---------------------------------------------------------------------------
// Row normalization: one warp per (n, v) row. view is [N, V, D].
// ---------------------------------------------------------------------------
__global__ void normalize_kernel(const float* __restrict__ view) {
    int gwarp = (blockIdx.x * blockDim.x + threadIdx.x) >> 5;
    int lane  = threadIdx.x & 31;
    if (gwarp >= NN * VV) return;
    int n = gwarp >> 1;
    int v = gwarp & 1;
    const float4* row = (const float4*)(view + ((size_t)n * VV + v) * DD);
    float4 x = row[lane];                       // 32 lanes * 4 = 128
    float ss = x.x * x.x + x.y * x.y + x.z * x.z + x.w * x.w;
    #pragma unroll
    for (int o = 16; o > 0; o >>= 1) ss += __shfl_xor_sync(0xffffffffu, ss, o);
    float nrm = sqrtf(ss);
    float s   = 1.0f / fmaxf(nrm, 1e-8f);
    float4 y; y.x = x.x * s; y.y = x.y * s; y.z = x.z * s; y.w = x.w * s;
    ((float4*)(&g_xn[v][n][0]))[lane] = y;
}

// ---------------------------------------------------------------------------
// Fused tile kernel: S-tile GEMM (128x128x128) + squared-error reduction.
// Grid: (NT, NT, VV); blocks with bj < bi exit (upper-triangular + diagonal).
// Off-diagonal tiles consume both Y[i,j] and Y[j,i] against S / S^T.
// ---------------------------------------------------------------------------
extern __shared__ float smem[];   // max(2*KC*ASTR, TILE*SSTR) floats

__global__ void __launch_bounds__(256, 2)
tile_loss_kernel(const float* __restrict__ simY) {
    const int bi = blockIdx.y;
    const int bj = blockIdx.x;
    const int v  = blockIdx.z;
    if (bj < bi) return;

    const int tx  = threadIdx.x;   // 0..15
    const int ty  = threadIdx.y;   // 0..15
    const int tid = ty * 16 + tx;  // 0..255

    float* As = smem;              // [KC][ASTR] k-major
    float* Bs = smem + KC * ASTR;

    const float* Xi = &g_xn[v][bi * TILE][0];
    const float* Xj = &g_xn[v][bj * TILE][0];

    float acc[8][8];
    #pragma unroll
    for (int i = 0; i < 8; i++)
        #pragma unroll
        for (int j = 0; j < 8; j++) acc[i][j] = 0.0f;

    for (int k0 = 0; k0 < DD; k0 += KC) {
        // Load 128x16 chunks of A and B, k-major in smem.
        #pragma unroll
        for (int l = 0; l < 2; l++) {
            int f   = l * 256 + tid;     // 0..511 float4 slots
            int row = f >> 2;            // 0..127
            int kq  = (f & 3) * 4;       // 0,4,8,12
            float4 a = *(const float4*)(Xi + row * DD + k0 + kq);
            As[(kq + 0) * ASTR + row] = a.x;
            As[(kq + 1) * ASTR + row] = a.y;
            As[(kq + 2) * ASTR + row] = a.z;
            As[(kq + 3) * ASTR + row] = a.w;
            float4 b = *(const float4*)(Xj + row * DD + k0 + kq);
            Bs[(kq + 0) * ASTR + row] = b.x;
            Bs[(kq + 1) * ASTR + row] = b.y;
            Bs[(kq + 2) * ASTR + row] = b.z;
            Bs[(kq + 3) * ASTR + row] = b.w;
        }
        __syncthreads();

        #pragma unroll
        for (int k = 0; k < KC; k++) {
            float af[8], bf[8];
            #pragma unroll
            for (int i = 0; i < 8; i++) af[i] = As[k * ASTR + ty * 8 + i];
            #pragma unroll
            for (int j = 0; j < 8; j++) bf[j] = Bs[k * ASTR + tx * 8 + j];
            #pragma unroll
            for (int i = 0; i < 8; i++)
                #pragma unroll
                for (int j = 0; j < 8; j++)
                    acc[i][j] = fmaf(af[i], bf[j], acc[i][j]);
        }
        __syncthreads();
    }

    // Stage S into smem (stride 129: conflict-free scalar reads in both orders).
    float* S = smem;
    #pragma unroll
    for (int i = 0; i < 8; i++)
        #pragma unroll
        for (int j = 0; j < 8; j++)
            S[(ty * 8 + i) * SSTR + (tx * 8 + j)] = acc[i][j];
    __syncthreads();

    float lsum = 0.0f;
    const size_t gi = (size_t)bi * TILE;
    const size_t gj = (size_t)bj * TILE;

    // Pass 1: (S[a][b] - Y[gi+a][gj+b])^2, coalesced Y reads.
    #pragma unroll 4
    for (int it = 0; it < 64; it++) {
        int e = it * 256 + tid;          // 0..16383
        int a = e >> 7;
        int b = e & 127;
        float y = simY[(gi + a) * NN + gj + b];
        float d = S[a * SSTR + b] - y;
        lsum = fmaf(d, d, lsum);
    }

    // Pass 2 (off-diagonal only): (S[q][p] - Y[gj+p][gi+q])^2, coalesced Y reads,
    // transposed-but-conflict-free S reads.
    if (bi != bj) {
        #pragma unroll 4
        for (int it = 0; it < 64; it++) {
            int e = it * 256 + tid;
            int p = e >> 7;
            int q = e & 127;
            float y = simY[(gj + p) * NN + gi + q];
            float d = S[q * SSTR + p] - y;
            lsum = fmaf(d, d, lsum);
        }
    }
    __syncthreads();

    // Block reduction (reuse smem), then one double atomic per block.
    float* red = smem;
    red[tid] = lsum;
    __syncthreads();
    #pragma unroll
    for (int s = 128; s > 0; s >>= 1) {
        if (tid < s) red[tid] += red[tid + s];
        __syncthreads();
    }
    if (tid == 0) atomicAdd(&g_acc, (double)red[0]);
}

// ---------------------------------------------------------------------------
// Finalize: loss = total_sum / N^2  (sum over views of per-view mean)
// ---------------------------------------------------------------------------
__global__ void finalize_kernel(float* __restrict__ out) {
    out[0] = (float)(g_acc / ((double)NN * (double)NN));
}

// ---------------------------------------------------------------------------
extern "C" void kernel_launch(void* const* d_in, const int* in_sizes, int n_in,
                              void* d_out, int out_size) {
    const float* view = (const float*)d_in[0];   // [N, V, D] float32
    const float* simY = (const float*)d_in[1];   // [N, N]   float32
    float* out = (float*)d_out;

    const int smem_bytes = TILE * SSTR * sizeof(float);  // 66048 B (> A/B tiles)
    cudaFuncSetAttribute(tile_loss_kernel,
                         cudaFuncAttributeMaxDynamicSharedMemorySize, smem_bytes);

    zero_acc_kernel<<<1, 1>>>();

    // 16384 rows, 8 warps (rows) per 256-thread block.
    normalize_kernel<<<(NN * VV) / 8, 256>>>(view);

    dim3 grid(NT, NT, VV);
    dim3 blk(16, 16, 1);
    tile_loss_kernel<<<grid, blk, smem_bytes>>>(simY);

    finalize_kernel<<<1, 1>>>(out);
}